// round 13
// baseline (speedup 1.0000x reference)
#include <cuda_runtime.h>
#include <cuda_fp16.h>
#include <math.h>
#include <cstdint>

// ============================================================================
// Problem constants
// ============================================================================
namespace {
constexpr int M   = 16384;   // B*S rows
constexpr int K   = 2048;    // n_embed
constexpr int E   = 64;      // num experts
constexpr int N2  = 128;     // fused output cols (W1 | W2)
constexpr int TK  = 8;       // top-k
constexpr int KC  = 32;      // k per pipeline stage
constexpr int NST = K / KC;  // 64 stages
constexpr int RSTR = 80;     // padded B row stride bytes (conflict-free ldmatrix)
constexpr int TILE = 128 * RSTR;       // 10240 B per split tile
constexpr int WSTAGE = 2 * TILE;       // 20480 B per stage (2 fp16 splits)
constexpr int NBUF = 4;                // cp.async pipeline depth
constexpr int LSTR = 132;              // smem logits row stride (floats)
constexpr int SMEM_TOTAL = NBUF * WSTAGE;  // 81920 B (>= 128*LSTR*4 = 67584)
constexpr float WSCALE     = 1024.0f;  // W pre-scale (avoids fp16 subnormal floor)
constexpr float INV_WSCALE = 1.0f / 1024.0f;
}

// Pre-split W blob: [kc(64)][split(2)][n(128)][RSTR bytes], fp16 k contiguous.
__device__ __align__(16) unsigned char gWB[(size_t)NST * WSTAGE];

// ============================================================================
// Helpers
// ============================================================================
__device__ __forceinline__ uint32_t smem_u32(const void* p) {
    uint32_t a;
    asm("{ .reg .u64 t; cvta.to.shared.u64 t, %1; cvt.u32.u64 %0, t; }" : "=r"(a) : "l"(p));
    return a;
}

#define CP_ASYNC16(dst, src) \
    asm volatile("cp.async.cg.shared.global [%0], [%1], 16;" :: "r"(dst), "l"(src))
#define CP_COMMIT() asm volatile("cp.async.commit_group;" ::: "memory")
#define CP_WAIT2()  asm volatile("cp.async.wait_group 2;" ::: "memory")

#define LDSM_X4(r, addr)                                                        \
    asm volatile("ldmatrix.sync.aligned.m8n8.x4.shared.b16 {%0,%1,%2,%3}, [%4];"\
        : "=r"((r)[0]), "=r"((r)[1]), "=r"((r)[2]), "=r"((r)[3]) : "r"(addr))

__device__ __forceinline__ void mma_acc(float* c, const uint32_t* a, const uint32_t* b) {
    asm volatile(
        "mma.sync.aligned.m16n8k16.row.col.f32.f16.f16.f32 "
        "{%0,%1,%2,%3}, {%4,%5,%6,%7}, {%8,%9}, {%0,%1,%2,%3};"
        : "+f"(c[0]), "+f"(c[1]), "+f"(c[2]), "+f"(c[3])
        : "r"(a[0]), "r"(a[1]), "r"(a[2]), "r"(a[3]), "r"(b[0]), "r"(b[1]));
}
__device__ __forceinline__ void mma_zero(float* d, const uint32_t* a, const uint32_t* b) {
    asm volatile(
        "mma.sync.aligned.m16n8k16.row.col.f32.f16.f16.f32 "
        "{%0,%1,%2,%3}, {%4,%5,%6,%7}, {%8,%9}, {%10,%11,%12,%13};"
        : "=f"(d[0]), "=f"(d[1]), "=f"(d[2]), "=f"(d[3])
        : "r"(a[0]), "r"(a[1]), "r"(a[2]), "r"(a[3]), "r"(b[0]), "r"(b[1]),
          "f"(0.f), "f"(0.f), "f"(0.f), "f"(0.f));
}

// fp16 2-way split of a float2 -> two packed half2 fragment registers.
__device__ __forceinline__ void sp2x2(float2 v, uint32_t& a0, uint32_t& a1) {
    __half2 h0 = __floats2half2_rn(v.x, v.y);
    float2 f0 = __half22float2(h0);
    __half2 h1 = __floats2half2_rn(v.x - f0.x, v.y - f0.y);
    a0 = *reinterpret_cast<uint32_t*>(&h0);
    a1 = *reinterpret_cast<uint32_t*>(&h1);
}

// ============================================================================
// Prep: scale W by 2^10, split into 2 fp16 blobs [kc][split][n][k].
// float2 along n: 2 experts per thread, 131072 threads.
// ============================================================================
__global__ __launch_bounds__(256) void prep_w_kernel(
    const float* __restrict__ W1, const float* __restrict__ W2)
{
    int t   = blockIdx.x * 256 + threadIdx.x;   // 0 .. 131071
    int kin = t & 31;
    int n2  = (t >> 5) & 63;                    // n pair (n = 2*n2, never straddles 64)
    int kc  = t >> 11;                          // 0..63
    int k   = kc * KC + kin;
    int n   = n2 * 2;

    float2 w = (n < E)
        ? *reinterpret_cast<const float2*>(W1 + (size_t)k * E + n)
        : *reinterpret_cast<const float2*>(W2 + (size_t)k * E + (n - E));
    w.x *= WSCALE; w.y *= WSCALE;

    __half hx0 = __float2half_rn(w.x);
    __half hy0 = __float2half_rn(w.y);
    __half hx1 = __float2half_rn(w.x - __half2float(hx0));
    __half hy1 = __float2half_rn(w.y - __half2float(hy0));

    size_t base = (size_t)kc * WSTAGE + (size_t)n * RSTR + kin * 2;
    *reinterpret_cast<unsigned short*>(gWB + base)               = __half_as_ushort(hx0);
    *reinterpret_cast<unsigned short*>(gWB + base + RSTR)        = __half_as_ushort(hy0);
    *reinterpret_cast<unsigned short*>(gWB + base + TILE)        = __half_as_ushort(hx1);
    *reinterpret_cast<unsigned short*>(gWB + base + TILE + RSTR) = __half_as_ushort(hy1);
}

// ============================================================================
// Fused GEMM + epilogue kernel.
// GEMM: mma.sync fp16x2-split, 3 products (h0g0 master via zero-C + RN FADD,
// h0g1 + h1g0 in correction mma-C chains). 128 rows/CTA, 8 warps x 16 rows.
// Epilogue (same CTA): stage logits to smem, then warp-per-row softmax/top-8.
// ============================================================================
__device__ __forceinline__ void issue_stage(uint32_t sb, int tid, int st) {
    const unsigned char* src = gWB + (size_t)st * WSTAGE;
    uint32_t dbase = sb + (uint32_t)(st & (NBUF - 1)) * WSTAGE;
    #pragma unroll
    for (int i = 0; i < 5; ++i) {            // 1280 chunks / 256 threads = 5
        int idx = tid + i * 256;
        CP_ASYNC16(dbase + idx * 16, src + (size_t)idx * 16);
    }
}

__device__ __forceinline__ void load_x(float2* v, const float* xr0, const float* xr1,
                                       int kt, int c2) {
    int kb = kt * KC + c2;
    v[0] = *reinterpret_cast<const float2*>(xr0 + kb);
    v[1] = *reinterpret_cast<const float2*>(xr0 + kb + 8);
    v[2] = *reinterpret_cast<const float2*>(xr0 + kb + 16);
    v[3] = *reinterpret_cast<const float2*>(xr0 + kb + 24);
    v[4] = *reinterpret_cast<const float2*>(xr1 + kb);
    v[5] = *reinterpret_cast<const float2*>(xr1 + kb + 8);
    v[6] = *reinterpret_cast<const float2*>(xr1 + kb + 16);
    v[7] = *reinterpret_cast<const float2*>(xr1 + kb + 24);
}

__global__ __launch_bounds__(256, 1) void gemm_fused_kernel(
    const float* __restrict__ x, const float* __restrict__ noise,
    const float* __restrict__ b1, const float* __restrict__ b2,
    float* __restrict__ out)
{
    extern __shared__ unsigned char sm[];
    const uint32_t sb = smem_u32(sm);
    const int tid  = threadIdx.x;
    const int wid  = tid >> 5;
    const int lane = tid & 31;
    const int row0 = blockIdx.x * 128;
    const int m0   = wid * 16;
    const int g    = lane >> 2;          // row-in-group 0..7
    const int c2   = (lane & 3) * 2;     // k-pair / col-pair base

    const float* xr0 = x + (size_t)(row0 + m0 + g) * K;
    const float* xr1 = xr0 + (size_t)8 * K;

    // B ldmatrix lane addressing
    const int rowB  = (lane & 7) + ((lane & 16) ? 8 : 0);
    const int colB8 = (lane & 8) ? 16 : 0;

    float master[16][4], corr[16][4];
    #pragma unroll
    for (int i = 0; i < 16; ++i)
        #pragma unroll
        for (int j = 0; j < 4; ++j) { master[i][j] = 0.f; corr[i][j] = 0.f; }

    // prologue: 3 stages of W in flight, stage-0 x in regs
    issue_stage(sb, tid, 0); CP_COMMIT();
    issue_stage(sb, tid, 1); CP_COMMIT();
    issue_stage(sb, tid, 2); CP_COMMIT();
    float2 xc[8], xn[8];
    load_x(xc, xr0, xr1, 0, c2);

    for (int kt = 0; kt < NST; ++kt) {
        CP_WAIT2();
        __syncthreads();
        if (kt + 3 < NST) issue_stage(sb, tid, kt + 3);
        CP_COMMIT();
        if (kt + 1 < NST) load_x(xn, xr0, xr1, kt + 1, c2);

        const uint32_t bufb = sb + (uint32_t)(kt & (NBUF - 1)) * WSTAGE;

        #pragma unroll
        for (int sub = 0; sub < 2; ++sub) {
            uint32_t A0[4], A1[4];
            sp2x2(xc[2 * sub],     A0[0], A1[0]);   // row g,    k0..k1
            sp2x2(xc[4 + 2 * sub], A0[1], A1[1]);   // row g+8,  k0..k1
            sp2x2(xc[2 * sub + 1], A0[2], A1[2]);   // row g,    k8..k9
            sp2x2(xc[5 + 2 * sub], A0[3], A1[3]);   // row g+8,  k8..k9

            const uint32_t k0b = sub * 32;
            #pragma unroll
            for (int np = 0; np < 8; ++np) {
                uint32_t b0[4], b1[4];
                uint32_t ab = bufb + (uint32_t)(np * 16 + rowB) * RSTR + k0b + colB8;
                LDSM_X4(b0, ab);
                LDSM_X4(b1, ab + TILE);

                float d[4];
                mma_zero(d, A0, &b0[0]);
                #pragma unroll
                for (int j = 0; j < 4; ++j) master[np * 2][j] += d[j];
                mma_acc(corr[np * 2], A0, &b1[0]);
                mma_acc(corr[np * 2], A1, &b0[0]);

                mma_zero(d, A0, &b0[2]);
                #pragma unroll
                for (int j = 0; j < 4; ++j) master[np * 2 + 1][j] += d[j];
                mma_acc(corr[np * 2 + 1], A0, &b1[2]);
                mma_acc(corr[np * 2 + 1], A1, &b0[2]);
            }
        }

        #pragma unroll
        for (int i = 0; i < 8; ++i) xc[i] = xn[i];
    }

    // ========================================================================
    // Fused epilogue. Stage logits (still WSCALE-scaled) into smem.
    // ========================================================================
    __syncthreads();                         // all LDSM done; reuse pipeline smem
    float* slin = reinterpret_cast<float*>(sm);   // [128][LSTR]

    #pragma unroll
    for (int np = 0; np < 16; ++np) {
        float2 vlo = make_float2(master[np][0] + corr[np][0],
                                 master[np][1] + corr[np][1]);
        float2 vhi = make_float2(master[np][2] + corr[np][2],
                                 master[np][3] + corr[np][3]);
        *reinterpret_cast<float2*>(slin + (m0 + g) * LSTR + np * 8 + c2)     = vlo;
        *reinterpret_cast<float2*>(slin + (m0 + g + 8) * LSTR + np * 8 + c2) = vhi;
    }
    __syncthreads();

    // warp-per-row softmax / top-8 over this warp's 16 rows
    const float NEG_INF = __int_as_float(0xff800000);
    float* osp   = out;
    float* oidx  = out + (size_t)M * E;
    float* ofull = oidx + (size_t)M * TK;

    for (int rr = 0; rr < 16; ++rr) {
        const int row = row0 + m0 + rr;
        const float* lin = slin + (m0 + rr) * LSTR;

        float l0 = lin[lane]      * INV_WSCALE + b1[lane];
        float l1 = lin[lane + 32] * INV_WSCALE + b1[lane + 32];
        float s0 = lin[64 + lane] * INV_WSCALE + b2[lane];
        float s1 = lin[96 + lane] * INV_WSCALE + b2[lane + 32];
        float n0 = noise[(size_t)row * E + lane];
        float n1 = noise[(size_t)row * E + 32 + lane];

        float sp0 = fmaxf(s0, 0.f) + log1pf(expf(-fabsf(s0)));
        float sp1 = fmaxf(s1, 0.f) + log1pf(expf(-fabsf(s1)));

        float m0v = l0 + n0 * sp0;
        float m1v = l1 + n1 * sp1;

        float mx = fmaxf(m0v, m1v);
        #pragma unroll
        for (int o = 16; o > 0; o >>= 1) mx = fmaxf(mx, __shfl_xor_sync(0xffffffffu, mx, o));

        float e0 = expf(m0v - mx), e1 = expf(m1v - mx);
        float sum = e0 + e1;
        #pragma unroll
        for (int o = 16; o > 0; o >>= 1) sum += __shfl_xor_sync(0xffffffffu, sum, o);

        float w0 = m0v, w1 = m1v;
        bool sel0 = false, sel1 = false;
        float ssum = 0.f;
        int my_idx = 0;
        #pragma unroll
        for (int kk = 0; kk < TK; ++kk) {
            float cv; int ci;
            if (w0 >= w1) { cv = w0; ci = lane; } else { cv = w1; ci = lane + 32; }
            #pragma unroll
            for (int o = 16; o > 0; o >>= 1) {
                float ov = __shfl_xor_sync(0xffffffffu, cv, o);
                int   oi = __shfl_xor_sync(0xffffffffu, ci, o);
                if (ov > cv || (ov == cv && oi < ci)) { cv = ov; ci = oi; }
            }
            ssum += expf(cv - mx);
            if (ci == lane)      { sel0 = true; w0 = NEG_INF; }
            if (ci == lane + 32) { sel1 = true; w1 = NEG_INF; }
            if (lane == kk) my_idx = ci;
        }

        const float inv_s  = 1.f / sum;
        const float inv_ss = 1.f / ssum;

        osp[(size_t)row * E + lane]        = sel0 ? e0 * inv_ss : 0.f;
        osp[(size_t)row * E + 32 + lane]   = sel1 ? e1 * inv_ss : 0.f;
        ofull[(size_t)row * E + lane]      = e0 * inv_s;
        ofull[(size_t)row * E + 32 + lane] = e1 * inv_s;
        if (lane < TK) oidx[(size_t)row * TK + lane] = (float)my_idx;
    }
}

// ============================================================================
// Launch
// ============================================================================
extern "C" void kernel_launch(void* const* d_in, const int* in_sizes, int n_in,
                              void* d_out, int out_size)
{
    (void)in_sizes; (void)n_in; (void)out_size;
    const float* x     = (const float*)d_in[0];
    const float* noise = (const float*)d_in[1];
    const float* W1    = (const float*)d_in[2];
    const float* b1    = (const float*)d_in[3];
    const float* W2    = (const float*)d_in[4];
    const float* b2    = (const float*)d_in[5];
    float* out = (float*)d_out;

    static bool attr_done = false;
    if (!attr_done) {
        cudaFuncSetAttribute(gemm_fused_kernel,
                             cudaFuncAttributeMaxDynamicSharedMemorySize, SMEM_TOTAL);
        attr_done = true;
    }

    prep_w_kernel<<<(K * N2 / 2) / 256, 256>>>(W1, W2);
    gemm_fused_kernel<<<M / 128, 256, SMEM_TOTAL>>>(x, noise, b1, b2, out);
}

// round 14
// speedup vs baseline: 1.2077x; 1.2077x over previous
#include <cuda_runtime.h>
#include <cuda_fp16.h>
#include <math.h>
#include <cstdint>

// ============================================================================
// Problem constants
// ============================================================================
namespace {
constexpr int M   = 16384;   // B*S rows
constexpr int K   = 2048;    // n_embed
constexpr int E   = 64;      // num experts
constexpr int N2  = 128;     // fused output cols (W1 | W2)
constexpr int TK  = 8;       // top-k
constexpr int KC  = 32;      // k per pipeline stage
constexpr int NST = K / KC;  // 64 stages
constexpr int RSTR = 80;     // padded B row stride bytes (conflict-free ldmatrix)
constexpr int TILE = 128 * RSTR;       // 10240 B per split tile
constexpr int WSTAGE = 2 * TILE;       // 20480 B per stage (2 fp16 splits)
constexpr int NBUF = 4;                // cp.async pipeline depth
constexpr int SMEM_TOTAL = NBUF * WSTAGE;  // 81920 B per CTA (x2 CTAs = 160KB/SM)
constexpr int CTA_ROWS = 64;           // rows per CTA (4 warps x 16)
constexpr int NTHR = 128;              // threads per CTA
constexpr float WSCALE     = 1024.0f;  // W pre-scale (avoids fp16 subnormal floor)
constexpr float INV_WSCALE = 1.0f / 1024.0f;
}

// ============================================================================
// Device scratch
// ============================================================================
// pre-bias linear outputs, scaled by WSCALE. cols 0..63 = x@W1, 64..127 = x@W2
__device__ float g_lin[(size_t)M * N2];
// Pre-split W blob: [kc(64)][split(2)][n(128)][RSTR bytes], fp16 k contiguous.
__device__ __align__(16) unsigned char gWB[(size_t)NST * WSTAGE];

// ============================================================================
// Helpers
// ============================================================================
__device__ __forceinline__ uint32_t smem_u32(const void* p) {
    uint32_t a;
    asm("{ .reg .u64 t; cvta.to.shared.u64 t, %1; cvt.u32.u64 %0, t; }" : "=r"(a) : "l"(p));
    return a;
}

#define CP_ASYNC16(dst, src) \
    asm volatile("cp.async.cg.shared.global [%0], [%1], 16;" :: "r"(dst), "l"(src))
#define CP_COMMIT() asm volatile("cp.async.commit_group;" ::: "memory")
#define CP_WAIT2()  asm volatile("cp.async.wait_group 2;" ::: "memory")

#define LDSM_X4(r, addr)                                                        \
    asm volatile("ldmatrix.sync.aligned.m8n8.x4.shared.b16 {%0,%1,%2,%3}, [%4];"\
        : "=r"((r)[0]), "=r"((r)[1]), "=r"((r)[2]), "=r"((r)[3]) : "r"(addr))

__device__ __forceinline__ void mma_acc(float* c, const uint32_t* a, const uint32_t* b) {
    asm volatile(
        "mma.sync.aligned.m16n8k16.row.col.f32.f16.f16.f32 "
        "{%0,%1,%2,%3}, {%4,%5,%6,%7}, {%8,%9}, {%0,%1,%2,%3};"
        : "+f"(c[0]), "+f"(c[1]), "+f"(c[2]), "+f"(c[3])
        : "r"(a[0]), "r"(a[1]), "r"(a[2]), "r"(a[3]), "r"(b[0]), "r"(b[1]));
}
__device__ __forceinline__ void mma_zero(float* d, const uint32_t* a, const uint32_t* b) {
    asm volatile(
        "mma.sync.aligned.m16n8k16.row.col.f32.f16.f16.f32 "
        "{%0,%1,%2,%3}, {%4,%5,%6,%7}, {%8,%9}, {%10,%11,%12,%13};"
        : "=f"(d[0]), "=f"(d[1]), "=f"(d[2]), "=f"(d[3])
        : "r"(a[0]), "r"(a[1]), "r"(a[2]), "r"(a[3]), "r"(b[0]), "r"(b[1]),
          "f"(0.f), "f"(0.f), "f"(0.f), "f"(0.f));
}

// fp16 2-way split of a float2 -> two packed half2 fragment registers.
__device__ __forceinline__ void sp2x2(float2 v, uint32_t& a0, uint32_t& a1) {
    __half2 h0 = __floats2half2_rn(v.x, v.y);
    float2 f0 = __half22float2(h0);
    __half2 h1 = __floats2half2_rn(v.x - f0.x, v.y - f0.y);
    a0 = *reinterpret_cast<uint32_t*>(&h0);
    a1 = *reinterpret_cast<uint32_t*>(&h1);
}

// ============================================================================
// Prep: scale W by 2^10, split into 2 fp16 blobs [kc][split][n][k].
// float2 along n: 2 experts per thread, 131072 threads.
// ============================================================================
__global__ __launch_bounds__(256) void prep_w_kernel(
    const float* __restrict__ W1, const float* __restrict__ W2)
{
    int t   = blockIdx.x * 256 + threadIdx.x;   // 0 .. 131071
    int kin = t & 31;
    int n2  = (t >> 5) & 63;                    // n pair (n = 2*n2, never straddles 64)
    int kc  = t >> 11;                          // 0..63
    int k   = kc * KC + kin;
    int n   = n2 * 2;

    float2 w = (n < E)
        ? *reinterpret_cast<const float2*>(W1 + (size_t)k * E + n)
        : *reinterpret_cast<const float2*>(W2 + (size_t)k * E + (n - E));
    w.x *= WSCALE; w.y *= WSCALE;

    __half hx0 = __float2half_rn(w.x);
    __half hy0 = __float2half_rn(w.y);
    __half hx1 = __float2half_rn(w.x - __half2float(hx0));
    __half hy1 = __float2half_rn(w.y - __half2float(hy0));

    size_t base = (size_t)kc * WSTAGE + (size_t)n * RSTR + kin * 2;
    *reinterpret_cast<unsigned short*>(gWB + base)               = __half_as_ushort(hx0);
    *reinterpret_cast<unsigned short*>(gWB + base + RSTR)        = __half_as_ushort(hy0);
    *reinterpret_cast<unsigned short*>(gWB + base + TILE)        = __half_as_ushort(hx1);
    *reinterpret_cast<unsigned short*>(gWB + base + TILE + RSTR) = __half_as_ushort(hy1);
}

// ============================================================================
// GEMM: mma.sync fp16x2-split, 3 products (h0g0 master, h0g1 + h1g0 corr).
// 64 rows/CTA (4 warps x 16 rows, all 128 cols), grid=256, 2 CTAs/SM.
// Main product: zero-C mma -> RN FFADD into master (no long RZ chains).
// W via 4-deep cp.async pipeline; x LDG'd to regs, split in-register.
// ============================================================================
__device__ __forceinline__ void issue_stage(uint32_t sb, int tid, int st) {
    const unsigned char* src = gWB + (size_t)st * WSTAGE;
    uint32_t dbase = sb + (uint32_t)(st & (NBUF - 1)) * WSTAGE;
    #pragma unroll
    for (int i = 0; i < 10; ++i) {           // 1280 chunks / 128 threads = 10
        int idx = tid + i * NTHR;
        CP_ASYNC16(dbase + idx * 16, src + (size_t)idx * 16);
    }
}

__device__ __forceinline__ void load_x(float2* v, const float* xr0, const float* xr1,
                                       int kt, int c2) {
    int kb = kt * KC + c2;
    v[0] = *reinterpret_cast<const float2*>(xr0 + kb);
    v[1] = *reinterpret_cast<const float2*>(xr0 + kb + 8);
    v[2] = *reinterpret_cast<const float2*>(xr0 + kb + 16);
    v[3] = *reinterpret_cast<const float2*>(xr0 + kb + 24);
    v[4] = *reinterpret_cast<const float2*>(xr1 + kb);
    v[5] = *reinterpret_cast<const float2*>(xr1 + kb + 8);
    v[6] = *reinterpret_cast<const float2*>(xr1 + kb + 16);
    v[7] = *reinterpret_cast<const float2*>(xr1 + kb + 24);
}

__global__ __launch_bounds__(NTHR, 2) void gemm_tc_kernel(const float* __restrict__ x)
{
    extern __shared__ unsigned char sm[];
    const uint32_t sb = smem_u32(sm);
    const int tid  = threadIdx.x;
    const int wid  = tid >> 5;
    const int lane = tid & 31;
    const int row0 = blockIdx.x * CTA_ROWS;
    const int m0   = wid * 16;
    const int g    = lane >> 2;          // row-in-group 0..7
    const int c2   = (lane & 3) * 2;     // k-pair base

    const float* xr0 = x + (size_t)(row0 + m0 + g) * K;
    const float* xr1 = xr0 + (size_t)8 * K;

    // B ldmatrix lane addressing
    const int rowB  = (lane & 7) + ((lane & 16) ? 8 : 0);
    const int colB8 = (lane & 8) ? 16 : 0;

    float master[16][4], corr[16][4];
    #pragma unroll
    for (int i = 0; i < 16; ++i)
        #pragma unroll
        for (int j = 0; j < 4; ++j) { master[i][j] = 0.f; corr[i][j] = 0.f; }

    // prologue: 3 stages of W in flight, stage-0 x in regs
    issue_stage(sb, tid, 0); CP_COMMIT();
    issue_stage(sb, tid, 1); CP_COMMIT();
    issue_stage(sb, tid, 2); CP_COMMIT();
    float2 xc[8], xn[8];
    load_x(xc, xr0, xr1, 0, c2);

    for (int kt = 0; kt < NST; ++kt) {
        CP_WAIT2();
        __syncthreads();
        if (kt + 3 < NST) issue_stage(sb, tid, kt + 3);
        CP_COMMIT();
        if (kt + 1 < NST) load_x(xn, xr0, xr1, kt + 1, c2);

        const uint32_t bufb = sb + (uint32_t)(kt & (NBUF - 1)) * WSTAGE;

        #pragma unroll
        for (int sub = 0; sub < 2; ++sub) {
            uint32_t A0[4], A1[4];
            sp2x2(xc[2 * sub],     A0[0], A1[0]);   // row g,    k0..k1
            sp2x2(xc[4 + 2 * sub], A0[1], A1[1]);   // row g+8,  k0..k1
            sp2x2(xc[2 * sub + 1], A0[2], A1[2]);   // row g,    k8..k9
            sp2x2(xc[5 + 2 * sub], A0[3], A1[3]);   // row g+8,  k8..k9

            const uint32_t k0b = sub * 32;
            #pragma unroll
            for (int np = 0; np < 8; ++np) {
                uint32_t b0[4], b1[4];
                uint32_t ab = bufb + (uint32_t)(np * 16 + rowB) * RSTR + k0b + colB8;
                LDSM_X4(b0, ab);
                LDSM_X4(b1, ab + TILE);

                float d[4];
                mma_zero(d, A0, &b0[0]);
                #pragma unroll
                for (int j = 0; j < 4; ++j) master[np * 2][j] += d[j];
                mma_acc(corr[np * 2], A0, &b1[0]);
                mma_acc(corr[np * 2], A1, &b0[0]);

                mma_zero(d, A0, &b0[2]);
                #pragma unroll
                for (int j = 0; j < 4; ++j) master[np * 2 + 1][j] += d[j];
                mma_acc(corr[np * 2 + 1], A0, &b1[2]);
                mma_acc(corr[np * 2 + 1], A1, &b0[2]);
            }
        }

        #pragma unroll
        for (int i = 0; i < 8; ++i) xc[i] = xn[i];
    }

    // ---- write results (master + corr, single RN add; still WSCALE-scaled) ----
    const int orow = row0 + m0 + g;
    #pragma unroll
    for (int np = 0; np < 16; ++np) {
        float2 vlo = make_float2(master[np][0] + corr[np][0],
                                 master[np][1] + corr[np][1]);
        float2 vhi = make_float2(master[np][2] + corr[np][2],
                                 master[np][3] + corr[np][3]);
        *reinterpret_cast<float2*>(g_lin + (size_t)orow * N2 + np * 8 + c2) = vlo;
        *reinterpret_cast<float2*>(g_lin + (size_t)(orow + 8) * N2 + np * 8 + c2) = vhi;
    }
}

// ============================================================================
// Epilogue: one warp per row. Applies INV_WSCALE to undo W pre-scaling.
// ============================================================================
__global__ __launch_bounds__(256) void epilogue_kernel(
    const float* __restrict__ noise,
    const float* __restrict__ b1, const float* __restrict__ b2,
    float* __restrict__ out)
{
    const float NEG_INF = __int_as_float(0xff800000);

    const int warp = (blockIdx.x * blockDim.x + threadIdx.x) >> 5;
    const int lane = threadIdx.x & 31;
    if (warp >= M) return;

    const float* lin = g_lin + (size_t)warp * N2;
    float l0 = lin[lane]      * INV_WSCALE + b1[lane];
    float l1 = lin[lane + 32] * INV_WSCALE + b1[lane + 32];
    float s0 = lin[64 + lane] * INV_WSCALE + b2[lane];
    float s1 = lin[96 + lane] * INV_WSCALE + b2[lane + 32];
    float n0 = noise[(size_t)warp * E + lane];
    float n1 = noise[(size_t)warp * E + 32 + lane];

    float sp0 = fmaxf(s0, 0.f) + log1pf(expf(-fabsf(s0)));
    float sp1 = fmaxf(s1, 0.f) + log1pf(expf(-fabsf(s1)));

    float m0 = l0 + n0 * sp0;
    float m1 = l1 + n1 * sp1;

    float mx = fmaxf(m0, m1);
    #pragma unroll
    for (int o = 16; o > 0; o >>= 1) mx = fmaxf(mx, __shfl_xor_sync(0xffffffffu, mx, o));

    float e0 = expf(m0 - mx), e1 = expf(m1 - mx);
    float sum = e0 + e1;
    #pragma unroll
    for (int o = 16; o > 0; o >>= 1) sum += __shfl_xor_sync(0xffffffffu, sum, o);

    float w0 = m0, w1 = m1;
    bool sel0 = false, sel1 = false;
    float ssum = 0.f;
    int my_idx = 0;
    #pragma unroll
    for (int kk = 0; kk < TK; ++kk) {
        float cv; int ci;
        if (w0 >= w1) { cv = w0; ci = lane; } else { cv = w1; ci = lane + 32; }
        #pragma unroll
        for (int o = 16; o > 0; o >>= 1) {
            float ov = __shfl_xor_sync(0xffffffffu, cv, o);
            int   oi = __shfl_xor_sync(0xffffffffu, ci, o);
            if (ov > cv || (ov == cv && oi < ci)) { cv = ov; ci = oi; }
        }
        ssum += expf(cv - mx);
        if (ci == lane)      { sel0 = true; w0 = NEG_INF; }
        if (ci == lane + 32) { sel1 = true; w1 = NEG_INF; }
        if (lane == kk) my_idx = ci;
    }

    const float inv_s  = 1.f / sum;
    const float inv_ss = 1.f / ssum;

    float* osp   = out;
    float* oidx  = out + (size_t)M * E;
    float* ofull = oidx + (size_t)M * TK;

    osp[(size_t)warp * E + lane]        = sel0 ? e0 * inv_ss : 0.f;
    osp[(size_t)warp * E + 32 + lane]   = sel1 ? e1 * inv_ss : 0.f;
    ofull[(size_t)warp * E + lane]      = e0 * inv_s;
    ofull[(size_t)warp * E + 32 + lane] = e1 * inv_s;
    if (lane < TK) oidx[(size_t)warp * TK + lane] = (float)my_idx;
}

// ============================================================================
// Launch
// ============================================================================
extern "C" void kernel_launch(void* const* d_in, const int* in_sizes, int n_in,
                              void* d_out, int out_size)
{
    (void)in_sizes; (void)n_in; (void)out_size;
    const float* x     = (const float*)d_in[0];
    const float* noise = (const float*)d_in[1];
    const float* W1    = (const float*)d_in[2];
    const float* b1    = (const float*)d_in[3];
    const float* W2    = (const float*)d_in[4];
    const float* b2    = (const float*)d_in[5];
    float* out = (float*)d_out;

    static bool attr_done = false;
    if (!attr_done) {
        cudaFuncSetAttribute(gemm_tc_kernel,
                             cudaFuncAttributeMaxDynamicSharedMemorySize, SMEM_TOTAL);
        attr_done = true;
    }

    prep_w_kernel<<<(K * N2 / 2) / 256, 256>>>(W1, W2);
    gemm_tc_kernel<<<M / CTA_ROWS, NTHR, SMEM_TOTAL>>>(x);
    epilogue_kernel<<<(M * 32 + 255) / 256, 256>>>(noise, b1, b2, out);
}

// round 16
// speedup vs baseline: 1.2760x; 1.0565x over previous
#include <cuda_runtime.h>
#include <cuda_fp16.h>
#include <math.h>
#include <cstdint>

// ============================================================================
// Problem constants
// ============================================================================
namespace {
constexpr int M   = 16384;   // B*S rows
constexpr int K   = 2048;    // n_embed
constexpr int E   = 64;      // num experts
constexpr int N2  = 128;     // fused output cols (W1 | W2)
constexpr int TK  = 8;       // top-k
constexpr int KC  = 32;      // k per pipeline stage
constexpr int NST = K / KC;  // 64 stages
constexpr int RSTR = 80;     // padded B row stride bytes (conflict-free ldmatrix)
constexpr int TILE = 128 * RSTR;       // 10240 B per W split tile
constexpr int WSTAGE = 2 * TILE;       // 20480 B (2 fp16 splits)
constexpr int XSTR_B = 144;            // x smem row stride bytes (36 floats)
constexpr int XTILE = 64 * XSTR_B;     // 9216 B (64 rows x 32 fp32, padded)
constexpr int STAGE = WSTAGE + XTILE;  // 29696 B
constexpr int NBUF = 3;
constexpr int SMEM_TOTAL = NBUF * STAGE;   // 89088 B (x2 CTAs = 178176)
constexpr int CTA_ROWS = 64;
constexpr int NTHR = 256;              // 8 warps: 4 row-groups x 2 col-halves
constexpr float WSCALE     = 1024.0f;
constexpr float INV_WSCALE = 1.0f / 1024.0f;
}

// ============================================================================
// Device scratch
// ============================================================================
__device__ float g_lin[(size_t)M * N2];  // WSCALE-scaled; cols 0..63=xW1, 64..127=xW2
// Pre-split W blob: [kc(64)][split(2)][n(128)][RSTR bytes], fp16 k contiguous.
__device__ __align__(16) unsigned char gWB[(size_t)NST * WSTAGE];

// ============================================================================
// Helpers
// ============================================================================
__device__ __forceinline__ uint32_t smem_u32(const void* p) {
    uint32_t a;
    asm("{ .reg .u64 t; cvta.to.shared.u64 t, %1; cvt.u32.u64 %0, t; }" : "=r"(a) : "l"(p));
    return a;
}

#define CP_ASYNC16(dst, src) \
    asm volatile("cp.async.cg.shared.global [%0], [%1], 16;" :: "r"(dst), "l"(src))
#define CP_COMMIT() asm volatile("cp.async.commit_group;" ::: "memory")
#define CP_WAIT1()  asm volatile("cp.async.wait_group 1;" ::: "memory")
#define CP_WAIT0()  asm volatile("cp.async.wait_group 0;" ::: "memory")

#define LDSM_X4(r, addr)                                                        \
    asm volatile("ldmatrix.sync.aligned.m8n8.x4.shared.b16 {%0,%1,%2,%3}, [%4];"\
        : "=r"((r)[0]), "=r"((r)[1]), "=r"((r)[2]), "=r"((r)[3]) : "r"(addr))

__device__ __forceinline__ void mma_acc(float* c, const uint32_t* a, const uint32_t* b) {
    asm volatile(
        "mma.sync.aligned.m16n8k16.row.col.f32.f16.f16.f32 "
        "{%0,%1,%2,%3}, {%4,%5,%6,%7}, {%8,%9}, {%0,%1,%2,%3};"
        : "+f"(c[0]), "+f"(c[1]), "+f"(c[2]), "+f"(c[3])
        : "r"(a[0]), "r"(a[1]), "r"(a[2]), "r"(a[3]), "r"(b[0]), "r"(b[1]));
}
__device__ __forceinline__ void mma_zero(float* d, const uint32_t* a, const uint32_t* b) {
    asm volatile(
        "mma.sync.aligned.m16n8k16.row.col.f32.f16.f16.f32 "
        "{%0,%1,%2,%3}, {%4,%5,%6,%7}, {%8,%9}, {%10,%11,%12,%13};"
        : "=f"(d[0]), "=f"(d[1]), "=f"(d[2]), "=f"(d[3])
        : "r"(a[0]), "r"(a[1]), "r"(a[2]), "r"(a[3]), "r"(b[0]), "r"(b[1]),
          "f"(0.f), "f"(0.f), "f"(0.f), "f"(0.f));
}

// fp16 2-way split of a float2 -> two packed half2 fragment registers.
__device__ __forceinline__ void sp2x2(float2 v, uint32_t& a0, uint32_t& a1) {
    __half2 h0 = __floats2half2_rn(v.x, v.y);
    float2 f0 = __half22float2(h0);
    __half2 h1 = __floats2half2_rn(v.x - f0.x, v.y - f0.y);
    a0 = *reinterpret_cast<uint32_t*>(&h0);
    a1 = *reinterpret_cast<uint32_t*>(&h1);
}

// ============================================================================
// Prep: scale W by 2^10, split into 2 fp16 blobs [kc][split][n][k].
// ============================================================================
__global__ __launch_bounds__(256) void prep_w_kernel(
    const float* __restrict__ W1, const float* __restrict__ W2)
{
    int t   = blockIdx.x * 256 + threadIdx.x;   // 0 .. 131071
    int kin = t & 31;
    int n2  = (t >> 5) & 63;                    // n pair (n = 2*n2, never straddles 64)
    int kc  = t >> 11;                          // 0..63
    int k   = kc * KC + kin;
    int n   = n2 * 2;

    float2 w = (n < E)
        ? *reinterpret_cast<const float2*>(W1 + (size_t)k * E + n)
        : *reinterpret_cast<const float2*>(W2 + (size_t)k * E + (n - E));
    w.x *= WSCALE; w.y *= WSCALE;

    __half hx0 = __float2half_rn(w.x);
    __half hy0 = __float2half_rn(w.y);
    __half hx1 = __float2half_rn(w.x - __half2float(hx0));
    __half hy1 = __float2half_rn(w.y - __half2float(hy0));

    size_t base = (size_t)kc * WSTAGE + (size_t)n * RSTR + kin * 2;
    *reinterpret_cast<unsigned short*>(gWB + base)               = __half_as_ushort(hx0);
    *reinterpret_cast<unsigned short*>(gWB + base + RSTR)        = __half_as_ushort(hy0);
    *reinterpret_cast<unsigned short*>(gWB + base + TILE)        = __half_as_ushort(hx1);
    *reinterpret_cast<unsigned short*>(gWB + base + TILE + RSTR) = __half_as_ushort(hy1);
}

// ============================================================================
// GEMM: mma.sync fp16x2-split, 3 products. 64 rows/CTA, 8 warps =
// 4 row-groups x 2 col-halves (16 rows x 64 cols per warp). grid=256,
// 2 CTAs/SM -> 4 warps/SMSP for latency hiding. W and x both staged via
// 3-deep cp.async pipeline; A fragments split in-register from smem x.
// ============================================================================
__device__ __forceinline__ void issue_stage(const float* __restrict__ x,
                                            uint32_t dbase, int tid, int st, int row0) {
    // W: 1280 chunks
    const unsigned char* wsrc = gWB + (size_t)st * WSTAGE;
    #pragma unroll
    for (int i = 0; i < 5; ++i) {
        int idx = tid + i * NTHR;
        CP_ASYNC16(dbase + idx * 16, wsrc + (size_t)idx * 16);
    }
    // x: 512 chunks (64 rows x 8x16B), padded row stride 144B in smem
    #pragma unroll
    for (int i = 0; i < 2; ++i) {
        int c = tid + i * NTHR;
        int row = c >> 3, part = c & 7;
        const float* src = x + (size_t)(row0 + row) * K + st * KC + part * 4;
        CP_ASYNC16(dbase + WSTAGE + row * XSTR_B + part * 16, src);
    }
}

__global__ __launch_bounds__(NTHR, 2) void gemm_tc_kernel(const float* __restrict__ x)
{
    extern __shared__ unsigned char sm[];
    const uint32_t sb = smem_u32(sm);
    const int tid  = threadIdx.x;
    const int wid  = tid >> 5;
    const int lane = tid & 31;
    const int row0 = blockIdx.x * CTA_ROWS;
    const int rg   = wid & 3;            // row group (16 rows)
    const int ch   = wid >> 2;           // column half (64 cols)
    const int m0   = rg * 16;
    const int g    = lane >> 2;          // row-in-group 0..7
    const int c2   = (lane & 3) * 2;     // k-pair / col-pair base

    // B ldmatrix lane addressing
    const int rowB  = (lane & 7) + ((lane & 16) ? 8 : 0);
    const int colB8 = (lane & 8) ? 16 : 0;

    float master[8][4], corr[8][4];
    #pragma unroll
    for (int i = 0; i < 8; ++i)
        #pragma unroll
        for (int j = 0; j < 4; ++j) { master[i][j] = 0.f; corr[i][j] = 0.f; }

    // prologue: 2 stages in flight
    issue_stage(x, sb + 0 * STAGE, tid, 0, row0); CP_COMMIT();
    issue_stage(x, sb + 1 * STAGE, tid, 1, row0); CP_COMMIT();

    int cur = 0, prev = 2;   // compute buffer; load target = buffer of stage kt-1
    for (int kt = 0; kt < NST; ++kt) {
        if (kt >= NST - 2) { CP_WAIT0(); } else { CP_WAIT1(); }
        __syncthreads();
        if (kt + 2 < NST) issue_stage(x, sb + prev * STAGE, tid, kt + 2, row0);
        CP_COMMIT();

        const uint32_t bufb = sb + (uint32_t)cur * STAGE;
        const unsigned char* xs = sm + cur * STAGE + WSTAGE;

        #pragma unroll
        for (int sub = 0; sub < 2; ++sub) {
            // A fragments from smem x (fp16 2-split in-register)
            const int kf = sub * 16 + c2;      // float index within 32-k chunk
            float2 v00 = *reinterpret_cast<const float2*>(xs + (m0 + g) * XSTR_B + kf * 4);
            float2 v01 = *reinterpret_cast<const float2*>(xs + (m0 + g) * XSTR_B + (kf + 8) * 4);
            float2 v10 = *reinterpret_cast<const float2*>(xs + (m0 + g + 8) * XSTR_B + kf * 4);
            float2 v11 = *reinterpret_cast<const float2*>(xs + (m0 + g + 8) * XSTR_B + (kf + 8) * 4);
            uint32_t A0[4], A1[4];
            sp2x2(v00, A0[0], A1[0]);
            sp2x2(v10, A0[1], A1[1]);
            sp2x2(v01, A0[2], A1[2]);
            sp2x2(v11, A0[3], A1[3]);

            const uint32_t k0b = sub * 32;
            #pragma unroll
            for (int np = 0; np < 4; ++np) {
                const int nrow = ch * 64 + np * 16 + rowB;
                uint32_t b0[4], b1[4];
                uint32_t ab = bufb + (uint32_t)nrow * RSTR + k0b + colB8;
                LDSM_X4(b0, ab);
                LDSM_X4(b1, ab + TILE);

                float d[4];
                mma_zero(d, A0, &b0[0]);
                #pragma unroll
                for (int j = 0; j < 4; ++j) master[np * 2][j] += d[j];
                mma_acc(corr[np * 2], A0, &b1[0]);
                mma_acc(corr[np * 2], A1, &b0[0]);

                mma_zero(d, A0, &b0[2]);
                #pragma unroll
                for (int j = 0; j < 4; ++j) master[np * 2 + 1][j] += d[j];
                mma_acc(corr[np * 2 + 1], A0, &b1[2]);
                mma_acc(corr[np * 2 + 1], A1, &b0[2]);
            }
        }

        prev = cur;
        cur = (cur == 2) ? 0 : cur + 1;
    }

    // ---- write results (master + corr, single RN add; WSCALE-scaled) ----
    const int orow = row0 + m0 + g;
    #pragma unroll
    for (int bb = 0; bb < 8; ++bb) {
        const int col = ch * 64 + bb * 8 + c2;
        float2 vlo = make_float2(master[bb][0] + corr[bb][0],
                                 master[bb][1] + corr[bb][1]);
        float2 vhi = make_float2(master[bb][2] + corr[bb][2],
                                 master[bb][3] + corr[bb][3]);
        *reinterpret_cast<float2*>(g_lin + (size_t)orow * N2 + col) = vlo;
        *reinterpret_cast<float2*>(g_lin + (size_t)(orow + 8) * N2 + col) = vhi;
    }
}

// ============================================================================
// Epilogue: one warp per row. Applies INV_WSCALE; ssum reuses e-values.
// ============================================================================
__global__ __launch_bounds__(256) void epilogue_kernel(
    const float* __restrict__ noise,
    const float* __restrict__ b1, const float* __restrict__ b2,
    float* __restrict__ out)
{
    const float NEG_INF = __int_as_float(0xff800000);

    const int warp = (blockIdx.x * blockDim.x + threadIdx.x) >> 5;
    const int lane = threadIdx.x & 31;
    if (warp >= M) return;

    const float* lin = g_lin + (size_t)warp * N2;
    float l0 = lin[lane]      * INV_WSCALE + b1[lane];
    float l1 = lin[lane + 32] * INV_WSCALE + b1[lane + 32];
    float s0 = lin[64 + lane] * INV_WSCALE + b2[lane];
    float s1 = lin[96 + lane] * INV_WSCALE + b2[lane + 32];
    float n0 = noise[(size_t)warp * E + lane];
    float n1 = noise[(size_t)warp * E + 32 + lane];

    float sp0 = fmaxf(s0, 0.f) + log1pf(expf(-fabsf(s0)));
    float sp1 = fmaxf(s1, 0.f) + log1pf(expf(-fabsf(s1)));

    float m0 = l0 + n0 * sp0;
    float m1 = l1 + n1 * sp1;

    float mx = fmaxf(m0, m1);
    #pragma unroll
    for (int o = 16; o > 0; o >>= 1) mx = fmaxf(mx, __shfl_xor_sync(0xffffffffu, mx, o));

    float e0 = expf(m0 - mx), e1 = expf(m1 - mx);
    float sum = e0 + e1;
    #pragma unroll
    for (int o = 16; o > 0; o >>= 1) sum += __shfl_xor_sync(0xffffffffu, sum, o);

    float w0 = m0, w1 = m1;
    bool sel0 = false, sel1 = false;
    int my_idx = 0;
    #pragma unroll
    for (int kk = 0; kk < TK; ++kk) {
        float cv; int ci;
        if (w0 >= w1) { cv = w0; ci = lane; } else { cv = w1; ci = lane + 32; }
        #pragma unroll
        for (int o = 16; o > 0; o >>= 1) {
            float ov = __shfl_xor_sync(0xffffffffu, cv, o);
            int   oi = __shfl_xor_sync(0xffffffffu, ci, o);
            if (ov > cv || (ov == cv && oi < ci)) { cv = ov; ci = oi; }
        }
        if (ci == lane)      { sel0 = true; w0 = NEG_INF; }
        if (ci == lane + 32) { sel1 = true; w1 = NEG_INF; }
        if (lane == kk) my_idx = ci;
    }

    // ssum from already-computed e-values of the selected experts
    float ssum = (sel0 ? e0 : 0.f) + (sel1 ? e1 : 0.f);
    #pragma unroll
    for (int o = 16; o > 0; o >>= 1) ssum += __shfl_xor_sync(0xffffffffu, ssum, o);

    const float inv_s  = 1.f / sum;
    const float inv_ss = 1.f / ssum;

    float* osp   = out;
    float* oidx  = out + (size_t)M * E;
    float* ofull = oidx + (size_t)M * TK;

    osp[(size_t)warp * E + lane]        = sel0 ? e0 * inv_ss : 0.f;
    osp[(size_t)warp * E + 32 + lane]   = sel1 ? e1 * inv_ss : 0.f;
    ofull[(size_t)warp * E + lane]      = e0 * inv_s;
    ofull[(size_t)warp * E + 32 + lane] = e1 * inv_s;
    if (lane < TK) oidx[(size_t)warp * TK + lane] = (float)my_idx;
}

// ============================================================================
// Launch
// ============================================================================
extern "C" void kernel_launch(void* const* d_in, const int* in_sizes, int n_in,
                              void* d_out, int out_size)
{
    (void)in_sizes; (void)n_in; (void)out_size;
    const float* x     = (const float*)d_in[0];
    const float* noise = (const float*)d_in[1];
    const float* W1    = (const float*)d_in[2];
    const float* b1    = (const float*)d_in[3];
    const float* W2    = (const float*)d_in[4];
    const float* b2    = (const float*)d_in[5];
    float* out = (float*)d_out;

    static bool attr_done = false;
    if (!attr_done) {
        cudaFuncSetAttribute(gemm_tc_kernel,
                             cudaFuncAttributeMaxDynamicSharedMemorySize, SMEM_TOTAL);
        attr_done = true;
    }

    prep_w_kernel<<<(K * N2 / 2) / 256, 256>>>(W1, W2);
    gemm_tc_kernel<<<M / CTA_ROWS, NTHR, SMEM_TOTAL>>>(x);
    epilogue_kernel<<<(M * 32 + 255) / 256, 256>>>(noise, b1, b2, out);
}

// round 17
// speedup vs baseline: 1.3462x; 1.0551x over previous
#include <cuda_runtime.h>
#include <cuda_fp16.h>
#include <math.h>
#include <cstdint>

// ============================================================================
// Problem constants
// ============================================================================
namespace {
constexpr int M   = 16384;   // B*S rows
constexpr int K   = 2048;    // n_embed
constexpr int E   = 64;      // num experts
constexpr int N2  = 128;     // fused output cols (W1 | W2)
constexpr int TK  = 8;       // top-k
constexpr int KC  = 32;      // k per pipeline stage
constexpr int NST = K / KC;  // 64 stages
constexpr int RSTR = 80;     // padded B row stride bytes (conflict-free ldmatrix)
constexpr int TILE = 128 * RSTR;       // 10240 B per W split tile
constexpr int WSTAGE = 2 * TILE;       // 20480 B (2 fp16 splits)
constexpr int XSTR_B = 144;            // x smem row stride bytes (36 floats)
constexpr int XTILE = 64 * XSTR_B;     // 9216 B (64 rows x 32 fp32, padded)
constexpr int STAGE = WSTAGE + XTILE;  // 29696 B
constexpr int NBUF = 3;
constexpr int SMEM_TOTAL = NBUF * STAGE;   // 89088 B (x2 CTAs = 178176)
constexpr int CTA_ROWS = 64;
constexpr int NTHR = 256;              // 8 warps: 4 row-groups x 2 col-halves
constexpr float WSCALE     = 1024.0f;
constexpr float INV_WSCALE = 1.0f / 1024.0f;
}

// ============================================================================
// Device scratch
// ============================================================================
__device__ float g_lin[(size_t)M * N2];  // WSCALE-scaled; cols 0..63=xW1, 64..127=xW2
// Pre-split W blob: [kc(64)][split(2)][n(128)][RSTR bytes], fp16 k contiguous.
__device__ __align__(16) unsigned char gWB[(size_t)NST * WSTAGE];

// ============================================================================
// Helpers
// ============================================================================
__device__ __forceinline__ uint32_t smem_u32(const void* p) {
    uint32_t a;
    asm("{ .reg .u64 t; cvta.to.shared.u64 t, %1; cvt.u32.u64 %0, t; }" : "=r"(a) : "l"(p));
    return a;
}

#define CP_ASYNC16(dst, src) \
    asm volatile("cp.async.cg.shared.global [%0], [%1], 16;" :: "r"(dst), "l"(src))
#define CP_COMMIT() asm volatile("cp.async.commit_group;" ::: "memory")
#define CP_WAIT1()  asm volatile("cp.async.wait_group 1;" ::: "memory")
#define CP_WAIT0()  asm volatile("cp.async.wait_group 0;" ::: "memory")

#define LDSM_X4(r, addr)                                                        \
    asm volatile("ldmatrix.sync.aligned.m8n8.x4.shared.b16 {%0,%1,%2,%3}, [%4];"\
        : "=r"((r)[0]), "=r"((r)[1]), "=r"((r)[2]), "=r"((r)[3]) : "r"(addr))

__device__ __forceinline__ void mma_acc(float* c, const uint32_t* a, const uint32_t* b) {
    asm volatile(
        "mma.sync.aligned.m16n8k16.row.col.f32.f16.f16.f32 "
        "{%0,%1,%2,%3}, {%4,%5,%6,%7}, {%8,%9}, {%0,%1,%2,%3};"
        : "+f"(c[0]), "+f"(c[1]), "+f"(c[2]), "+f"(c[3])
        : "r"(a[0]), "r"(a[1]), "r"(a[2]), "r"(a[3]), "r"(b[0]), "r"(b[1]));
}

// fp16 2-way split of a float2 -> two packed half2 fragment registers.
__device__ __forceinline__ void sp2x2(float2 v, uint32_t& a0, uint32_t& a1) {
    __half2 h0 = __floats2half2_rn(v.x, v.y);
    float2 f0 = __half22float2(h0);
    __half2 h1 = __floats2half2_rn(v.x - f0.x, v.y - f0.y);
    a0 = *reinterpret_cast<uint32_t*>(&h0);
    a1 = *reinterpret_cast<uint32_t*>(&h1);
}

// ============================================================================
// Prep: scale W by 2^10, split into 2 fp16 blobs [kc][split][n][k].
// ============================================================================
__global__ __launch_bounds__(256) void prep_w_kernel(
    const float* __restrict__ W1, const float* __restrict__ W2)
{
    int t   = blockIdx.x * 256 + threadIdx.x;   // 0 .. 131071
    int kin = t & 31;
    int n2  = (t >> 5) & 63;                    // n pair (n = 2*n2, never straddles 64)
    int kc  = t >> 11;                          // 0..63
    int k   = kc * KC + kin;
    int n   = n2 * 2;

    float2 w = (n < E)
        ? *reinterpret_cast<const float2*>(W1 + (size_t)k * E + n)
        : *reinterpret_cast<const float2*>(W2 + (size_t)k * E + (n - E));
    w.x *= WSCALE; w.y *= WSCALE;

    __half hx0 = __float2half_rn(w.x);
    __half hy0 = __float2half_rn(w.y);
    __half hx1 = __float2half_rn(w.x - __half2float(hx0));
    __half hy1 = __float2half_rn(w.y - __half2float(hy0));

    size_t base = (size_t)kc * WSTAGE + (size_t)n * RSTR + kin * 2;
    *reinterpret_cast<unsigned short*>(gWB + base)               = __half_as_ushort(hx0);
    *reinterpret_cast<unsigned short*>(gWB + base + RSTR)        = __half_as_ushort(hy0);
    *reinterpret_cast<unsigned short*>(gWB + base + TILE)        = __half_as_ushort(hx1);
    *reinterpret_cast<unsigned short*>(gWB + base + TILE + RSTR) = __half_as_ushort(hy1);
}

// ============================================================================
// GEMM: mma.sync fp16x2-split, 3 products. 64 rows/CTA, 8 warps =
// 4 row-groups x 2 col-halves (16 rows x 64 cols per warp). grid=256,
// 2 CTAs/SM -> 4 warps/SMSP. Master AND corr both accumulate in mma-C
// chains (no per-stage FADDs); master chain kept separate from the
// 2^-11-scale corr chain so fp32 accumulation precision is preserved.
// Single RN add at writeout.
// ============================================================================
__device__ __forceinline__ void issue_stage(const float* __restrict__ x,
                                            uint32_t dbase, int tid, int st, int row0) {
    // W: 1280 chunks
    const unsigned char* wsrc = gWB + (size_t)st * WSTAGE;
    #pragma unroll
    for (int i = 0; i < 5; ++i) {
        int idx = tid + i * NTHR;
        CP_ASYNC16(dbase + idx * 16, wsrc + (size_t)idx * 16);
    }
    // x: 512 chunks (64 rows x 8x16B), padded row stride 144B in smem
    #pragma unroll
    for (int i = 0; i < 2; ++i) {
        int c = tid + i * NTHR;
        int row = c >> 3, part = c & 7;
        const float* src = x + (size_t)(row0 + row) * K + st * KC + part * 4;
        CP_ASYNC16(dbase + WSTAGE + row * XSTR_B + part * 16, src);
    }
}

__global__ __launch_bounds__(NTHR, 2) void gemm_tc_kernel(const float* __restrict__ x)
{
    extern __shared__ unsigned char sm[];
    const uint32_t sb = smem_u32(sm);
    const int tid  = threadIdx.x;
    const int wid  = tid >> 5;
    const int lane = tid & 31;
    const int row0 = blockIdx.x * CTA_ROWS;
    const int rg   = wid & 3;            // row group (16 rows)
    const int ch   = wid >> 2;           // column half (64 cols)
    const int m0   = rg * 16;
    const int g    = lane >> 2;          // row-in-group 0..7
    const int c2   = (lane & 3) * 2;     // k-pair / col-pair base

    // B ldmatrix lane addressing
    const int rowB  = (lane & 7) + ((lane & 16) ? 8 : 0);
    const int colB8 = (lane & 8) ? 16 : 0;

    float master[8][4], corr[8][4];
    #pragma unroll
    for (int i = 0; i < 8; ++i)
        #pragma unroll
        for (int j = 0; j < 4; ++j) { master[i][j] = 0.f; corr[i][j] = 0.f; }

    // prologue: 2 stages in flight
    issue_stage(x, sb + 0 * STAGE, tid, 0, row0); CP_COMMIT();
    issue_stage(x, sb + 1 * STAGE, tid, 1, row0); CP_COMMIT();

    int cur = 0, prev = 2;   // compute buffer; load target = buffer of stage kt-1
    for (int kt = 0; kt < NST; ++kt) {
        if (kt >= NST - 2) { CP_WAIT0(); } else { CP_WAIT1(); }
        __syncthreads();
        if (kt + 2 < NST) issue_stage(x, sb + prev * STAGE, tid, kt + 2, row0);
        CP_COMMIT();

        const uint32_t bufb = sb + (uint32_t)cur * STAGE;
        const unsigned char* xs = sm + cur * STAGE + WSTAGE;

        #pragma unroll
        for (int sub = 0; sub < 2; ++sub) {
            // A fragments from smem x (fp16 2-split in-register)
            const int kf = sub * 16 + c2;      // float index within 32-k chunk
            float2 v00 = *reinterpret_cast<const float2*>(xs + (m0 + g) * XSTR_B + kf * 4);
            float2 v01 = *reinterpret_cast<const float2*>(xs + (m0 + g) * XSTR_B + (kf + 8) * 4);
            float2 v10 = *reinterpret_cast<const float2*>(xs + (m0 + g + 8) * XSTR_B + kf * 4);
            float2 v11 = *reinterpret_cast<const float2*>(xs + (m0 + g + 8) * XSTR_B + (kf + 8) * 4);
            uint32_t A0[4], A1[4];
            sp2x2(v00, A0[0], A1[0]);
            sp2x2(v10, A0[1], A1[1]);
            sp2x2(v01, A0[2], A1[2]);
            sp2x2(v11, A0[3], A1[3]);

            const uint32_t k0b = sub * 32;
            #pragma unroll
            for (int np = 0; np < 4; ++np) {
                const int nrow = ch * 64 + np * 16 + rowB;
                uint32_t b0[4], b1[4];
                uint32_t ab = bufb + (uint32_t)nrow * RSTR + k0b + colB8;
                LDSM_X4(b0, ab);
                LDSM_X4(b1, ab + TILE);

                // master chain: h0*g0 only (fp32 C-accumulate in tensor core)
                mma_acc(master[np * 2], A0, &b0[0]);
                mma_acc(master[np * 2 + 1], A0, &b0[2]);
                // corr chain: h0*g1 + h1*g0 (tiny magnitudes, isolated chain)
                mma_acc(corr[np * 2], A0, &b1[0]);
                mma_acc(corr[np * 2], A1, &b0[0]);
                mma_acc(corr[np * 2 + 1], A0, &b1[2]);
                mma_acc(corr[np * 2 + 1], A1, &b0[2]);
            }
        }

        prev = cur;
        cur = (cur == 2) ? 0 : cur + 1;
    }

    // ---- write results (master + corr, single RN add; WSCALE-scaled) ----
    const int orow = row0 + m0 + g;
    #pragma unroll
    for (int bb = 0; bb < 8; ++bb) {
        const int col = ch * 64 + bb * 8 + c2;
        float2 vlo = make_float2(master[bb][0] + corr[bb][0],
                                 master[bb][1] + corr[bb][1]);
        float2 vhi = make_float2(master[bb][2] + corr[bb][2],
                                 master[bb][3] + corr[bb][3]);
        *reinterpret_cast<float2*>(g_lin + (size_t)orow * N2 + col) = vlo;
        *reinterpret_cast<float2*>(g_lin + (size_t)(orow + 8) * N2 + col) = vhi;
    }
}

// ============================================================================
// Epilogue: one warp per row. Applies INV_WSCALE; ssum reuses e-values.
// ============================================================================
__global__ __launch_bounds__(256) void epilogue_kernel(
    const float* __restrict__ noise,
    const float* __restrict__ b1, const float* __restrict__ b2,
    float* __restrict__ out)
{
    const float NEG_INF = __int_as_float(0xff800000);

    const int warp = (blockIdx.x * blockDim.x + threadIdx.x) >> 5;
    const int lane = threadIdx.x & 31;
    if (warp >= M) return;

    const float* lin = g_lin + (size_t)warp * N2;
    float l0 = lin[lane]      * INV_WSCALE + b1[lane];
    float l1 = lin[lane + 32] * INV_WSCALE + b1[lane + 32];
    float s0 = lin[64 + lane] * INV_WSCALE + b2[lane];
    float s1 = lin[96 + lane] * INV_WSCALE + b2[lane + 32];
    float n0 = noise[(size_t)warp * E + lane];
    float n1 = noise[(size_t)warp * E + 32 + lane];

    float sp0 = fmaxf(s0, 0.f) + log1pf(expf(-fabsf(s0)));
    float sp1 = fmaxf(s1, 0.f) + log1pf(expf(-fabsf(s1)));

    float m0 = l0 + n0 * sp0;
    float m1 = l1 + n1 * sp1;

    float mx = fmaxf(m0, m1);
    #pragma unroll
    for (int o = 16; o > 0; o >>= 1) mx = fmaxf(mx, __shfl_xor_sync(0xffffffffu, mx, o));

    float e0 = expf(m0 - mx), e1 = expf(m1 - mx);
    float sum = e0 + e1;
    #pragma unroll
    for (int o = 16; o > 0; o >>= 1) sum += __shfl_xor_sync(0xffffffffu, sum, o);

    float w0 = m0, w1 = m1;
    bool sel0 = false, sel1 = false;
    int my_idx = 0;
    #pragma unroll
    for (int kk = 0; kk < TK; ++kk) {
        float cv; int ci;
        if (w0 >= w1) { cv = w0; ci = lane; } else { cv = w1; ci = lane + 32; }
        #pragma unroll
        for (int o = 16; o > 0; o >>= 1) {
            float ov = __shfl_xor_sync(0xffffffffu, cv, o);
            int   oi = __shfl_xor_sync(0xffffffffu, ci, o);
            if (ov > cv || (ov == cv && oi < ci)) { cv = ov; ci = oi; }
        }
        if (ci == lane)      { sel0 = true; w0 = NEG_INF; }
        if (ci == lane + 32) { sel1 = true; w1 = NEG_INF; }
        if (lane == kk) my_idx = ci;
    }

    float ssum = (sel0 ? e0 : 0.f) + (sel1 ? e1 : 0.f);
    #pragma unroll
    for (int o = 16; o > 0; o >>= 1) ssum += __shfl_xor_sync(0xffffffffu, ssum, o);

    const float inv_s  = 1.f / sum;
    const float inv_ss = 1.f / ssum;

    float* osp   = out;
    float* oidx  = out + (size_t)M * E;
    float* ofull = oidx + (size_t)M * TK;

    osp[(size_t)warp * E + lane]        = sel0 ? e0 * inv_ss : 0.f;
    osp[(size_t)warp * E + 32 + lane]   = sel1 ? e1 * inv_ss : 0.f;
    ofull[(size_t)warp * E + lane]      = e0 * inv_s;
    ofull[(size_t)warp * E + 32 + lane] = e1 * inv_s;
    if (lane < TK) oidx[(size_t)warp * TK + lane] = (float)my_idx;
}

// ============================================================================
// Launch
// ============================================================================
extern "C" void kernel_launch(void* const* d_in, const int* in_sizes, int n_in,
                              void* d_out, int out_size)
{
    (void)in_sizes; (void)n_in; (void)out_size;
    const float* x     = (const float*)d_in[0];
    const float* noise = (const float*)d_in[1];
    const float* W1    = (const float*)d_in[2];
    const float* b1    = (const float*)d_in[3];
    const float* W2    = (const float*)d_in[4];
    const float* b2    = (const float*)d_in[5];
    float* out = (float*)d_out;

    static bool attr_done = false;
    if (!attr_done) {
        cudaFuncSetAttribute(gemm_tc_kernel,
                             cudaFuncAttributeMaxDynamicSharedMemorySize, SMEM_TOTAL);
        attr_done = true;
    }

    prep_w_kernel<<<(K * N2 / 2) / 256, 256>>>(W1, W2);
    gemm_tc_kernel<<<M / CTA_ROWS, NTHR, SMEM_TOTAL>>>(x);
    epilogue_kernel<<<(M * 32 + 255) / 256, 256>>>(noise, b1, b2, out);
}